// round 7
// baseline (speedup 1.0000x reference)
#include <cuda_runtime.h>
#include <cuda_bf16.h>

// activations [B=64, C=256, L=512] fp32 -> BatchNorm1d (batch stats) -> 16-step
// ternary LIF (snntorch Leaky, subtract reset) -> mean spike over steps.
//
// Algebra: reset_t = fire(mem_t) = spk_{t-1}, so one fire() per step:
//   m = 0.9*m + x - spk_prev;  spk = (m>1) - (m<-1);  s += spk
// We carry n = -spk = (m<-1) - (m>1), built from two FSET (set.gt.f32.f32,
// 1.0f/0.0f result) plus one FADD. Packed f32x2 FFMA/FADD carry m and s.
// Output is -S/16.

#define NB 64
#define NC 256
#define NL 512
#define ELEMS_PER_CH (NB * NL)          // 32768
#define F4_PER_CH (ELEMS_PER_CH / 4)    // 8192
#define TOTAL_F4 (NB * NC * NL / 4)     // 2097152

__device__ float g_scale[NC];
__device__ float g_shift[NC];

typedef unsigned long long u64;

// ---------- packed f32x2 helpers ----------
__device__ __forceinline__ u64 f32x2_fma(u64 a, u64 b, u64 c) {
    u64 r;
    asm("fma.rn.f32x2 %0, %1, %2, %3;" : "=l"(r) : "l"(a), "l"(b), "l"(c));
    return r;
}
__device__ __forceinline__ u64 f32x2_add(u64 a, u64 b) {
    u64 r;
    asm("add.rn.f32x2 %0, %1, %2;" : "=l"(r) : "l"(a), "l"(b));
    return r;
}
__device__ __forceinline__ u64 pk(float lo, float hi) {
    u64 r;
    asm("mov.b64 %0, {%1, %2};" : "=l"(r) : "f"(lo), "f"(hi));
    return r;
}
__device__ __forceinline__ void upk(u64 v, float& lo, float& hi) {
    asm("mov.b64 {%0, %1}, %2;" : "=f"(lo), "=f"(hi) : "l"(v));
}

// set.gt -> 1.0f if a > b else 0.0f (single SASS FSET, alu pipe)
__device__ __forceinline__ float fset_gt(float a, float b) {
    float r;
    asm("set.gt.f32.f32 %0, %1, %2;" : "=f"(r) : "f"(a), "f"(b));
    return r;
}

// negated ternary fire: -spk = (m < -1) - (m > 1). Strict inequalities match
// the reference heaviside (m-1 > 0) / (-1-m > 0).
__device__ __forceinline__ float neg_fire(float m) {
    return fset_gt(-1.0f, m) - fset_gt(m, 1.0f);
}

// ---------- Pass 1: per-channel BN stats -> folded (scale, shift) ----------
__global__ __launch_bounds__(512) void bn_stats_kernel(
    const float* __restrict__ act,
    const float* __restrict__ w,
    const float* __restrict__ bias)
{
    const int c = blockIdx.x;          // one block per channel
    const int tid = threadIdx.x;       // 512 threads
    const float4* a4 = reinterpret_cast<const float4*>(act);

    float s1 = 0.f, s2 = 0.f;
    #pragma unroll 4
    for (int i = tid; i < F4_PER_CH; i += 512) {
        const int b = i >> 7;          // 128 float4 per (b,c) row
        const int l4 = i & 127;
        float4 v = a4[(b * NC + c) * 128 + l4];
        s1 += (v.x + v.y) + (v.z + v.w);
        s2 += v.x * v.x + v.y * v.y + v.z * v.z + v.w * v.w;
    }

    #pragma unroll
    for (int o = 16; o; o >>= 1) {
        s1 += __shfl_down_sync(0xffffffffu, s1, o);
        s2 += __shfl_down_sync(0xffffffffu, s2, o);
    }
    __shared__ float sh1[16], sh2[16];
    const int wid = tid >> 5, lid = tid & 31;
    if (lid == 0) { sh1[wid] = s1; sh2[wid] = s2; }
    __syncthreads();
    if (tid == 0) {
        float t1 = 0.f, t2 = 0.f;
        #pragma unroll
        for (int k = 0; k < 16; ++k) { t1 += sh1[k]; t2 += sh2[k]; }
        const float inv_n = 1.0f / (float)ELEMS_PER_CH;
        const float mean = t1 * inv_n;
        const float var = fmaf(t2, inv_n, -mean * mean);   // biased var (jnp.var)
        const float sc = w[c] * rsqrtf(var + 1e-5f);
        g_scale[c] = sc;
        g_shift[c] = fmaf(-mean, sc, bias[c]);
    }
}

// ---------- Pass 2: BN apply + 16-step ternary LIF (8 elems/thread) ----------
__global__ __launch_bounds__(256) void lif_kernel(
    const float4* __restrict__ in, float4* __restrict__ out)
{
    const int gid = blockIdx.x * blockDim.x + threadIdx.x;   // [0, TOTAL_F4/2)
    const int f = gid * 2;                                    // even float4 index
    // 128 float4 per (b,c) row; row length even -> f and f+1 share a channel
    const int ch = (f >> 7) & (NC - 1);

    const float sc = g_scale[ch];
    const float sh = g_shift[ch];

    const float4 a = in[f];
    const float4 b = in[f + 1];

    u64 X[4];
    X[0] = pk(fmaf(a.x, sc, sh), fmaf(a.y, sc, sh));
    X[1] = pk(fmaf(a.z, sc, sh), fmaf(a.w, sc, sh));
    X[2] = pk(fmaf(b.x, sc, sh), fmaf(b.y, sc, sh));
    X[3] = pk(fmaf(b.z, sc, sh), fmaf(b.w, sc, sh));

    const u64 BETA2 = 0x3F6666663F666666ULL;  // (0.9f, 0.9f)

    u64 M[4] = {0ull, 0ull, 0ull, 0ull};
    u64 N[4] = {0ull, 0ull, 0ull, 0ull};   // N = -spk_prev
    u64 S[4] = {0ull, 0ull, 0ull, 0ull};   // S = sum(-spk)

    #pragma unroll
    for (int t = 0; t < 16; ++t) {
        #pragma unroll
        for (int j = 0; j < 4; ++j) {
            M[j] = f32x2_add(f32x2_fma(BETA2, M[j], X[j]), N[j]);  // m = .9m + x - spk
            float m0, m1;
            upk(M[j], m0, m1);
            N[j] = pk(neg_fire(m0), neg_fire(m1));
            S[j] = f32x2_add(S[j], N[j]);
        }
    }

    float4 o0, o1;
    {
        float s0, s1;
        upk(S[0], s0, s1); o0.x = s0 * -0.0625f; o0.y = s1 * -0.0625f;
        upk(S[1], s0, s1); o0.z = s0 * -0.0625f; o0.w = s1 * -0.0625f;
        upk(S[2], s0, s1); o1.x = s0 * -0.0625f; o1.y = s1 * -0.0625f;
        upk(S[3], s0, s1); o1.z = s0 * -0.0625f; o1.w = s1 * -0.0625f;
    }
    out[f] = o0;
    out[f + 1] = o1;
}

extern "C" void kernel_launch(void* const* d_in, const int* in_sizes, int n_in,
                              void* d_out, int out_size)
{
    const float* act  = (const float*)d_in[0];
    const float* w    = (const float*)d_in[1];
    const float* bias = (const float*)d_in[2];
    float* out = (float*)d_out;

    bn_stats_kernel<<<NC, 512>>>(act, w, bias);
    lif_kernel<<<TOTAL_F4 / 2 / 256, 256>>>(
        reinterpret_cast<const float4*>(act),
        reinterpret_cast<float4*>(out));
}